// round 17
// baseline (speedup 1.0000x reference)
#include <cuda_runtime.h>
#include <cuda_bf16.h>
#include <mma.h>
#include <cstdint>

using namespace nvcuda;

// Problem constants
constexpr int kN  = 50000;
constexpr int kE  = 800000;
constexpr int kG  = 128;
constexpr int kD  = 128;
constexpr int kH  = 512;
constexpr int kH2 = 1024;
constexpr int kL  = 4;
#define BNS 0.9999950000374997f   // 1/sqrt(1+1e-5)

// ---------------- scratch (no cudaMalloc allowed) ----------------
__device__ float g_h   [(size_t)kN * kH];
__device__ float g_zin [(size_t)kN * kH];
__device__ float g_y1  [(size_t)kN * kH2];
__device__ float g_vf  [kG * kH];
__device__ float g_sa  [kN];
__device__ int   g_goff[kG + 1];

// CSR structures
__device__ int g_deg   [kN];
__device__ int g_cur   [kN];
__device__ int g_rowptr[kN + 1];
__device__ int g_esrc  [kE];

// int8 activation buffers (2-term), max width kH2
__device__ signed char g_a8h[(size_t)kN * kH2];
__device__ signed char g_a8l[(size_t)kN * kH2];

// int8 weights (2-term), layout [K, Nc] row-major
constexpr size_t OFF_c1W1 = 0;                            // [128,1024]
constexpr size_t OFF_c1W2 = OFF_c1W1 + 128 * 1024;        // [1024,512]
constexpr size_t OFF_csW1 = OFF_c1W2 + 1024 * 512;        // 4 x [512,1024]
constexpr size_t OFF_csW2 = OFF_csW1 + 4ull * 512 * 1024; // 4 x [1024,512]
constexpr size_t W8_TOTAL = OFF_csW2 + 4ull * 1024 * 512;
__device__ signed char g_w8h[W8_TOTAL];
__device__ signed char g_w8l[W8_TOTAL];
// per-column scales for the 10 int8 matrices
constexpr int SW_c1W1 = 0;            // 1024
constexpr int SW_c1W2 = 1024;         // 512
constexpr int SW_cs   = 1536;         // per layer: 1024 (W1) + 512 (W2)
constexpr int SW_TOT  = 1536 + 4 * 1536;
__device__ float g_sw[SW_TOT];

// bf16 path (virtual-node MLP only)
__device__ __nv_bfloat16 g_vwhi[2ull * 512 * 1024];  // vW1 then vW2
__device__ __nv_bfloat16 g_vwlo[2ull * 512 * 1024];
constexpr size_t OFF_vW1 = 0;
constexpr size_t OFF_vW2 = 512 * 1024;
__device__ __nv_bfloat16 g_phi[kG * kH];
__device__ __nv_bfloat16 g_plo[kG * kH];
__device__ __nv_bfloat16 g_qhi[kG * kH2];
__device__ __nv_bfloat16 g_qlo[kG * kH2];

// ---------------- helpers ----------------
__device__ __forceinline__ uint32_t smem_u32(const void* p) {
    uint32_t a;
    asm("{ .reg .u64 t; cvta.to.shared.u64 t, %1; cvt.u32.u64 %0, t; }" : "=r"(a) : "l"(p));
    return a;
}
__device__ __forceinline__ void cp16(uint32_t saddr, const void* gaddr) {
    asm volatile("cp.async.cg.shared.global [%0], [%1], 16;" :: "r"(saddr), "l"(gaddr) : "memory");
}
#define CP_COMMIT() asm volatile("cp.async.commit_group;" ::: "memory")
#define CP_WAIT(n)  asm volatile("cp.async.wait_group %0;" :: "n"(n) : "memory")

__device__ __forceinline__ void split4(float4 v, uint2& uh, uint2& ul) {
    unsigned short hx = __bfloat16_as_ushort(__float2bfloat16(v.x));
    unsigned short hy = __bfloat16_as_ushort(__float2bfloat16(v.y));
    unsigned short hz = __bfloat16_as_ushort(__float2bfloat16(v.z));
    unsigned short hw = __bfloat16_as_ushort(__float2bfloat16(v.w));
    float fx = __bfloat162float(__ushort_as_bfloat16(hx));
    float fy = __bfloat162float(__ushort_as_bfloat16(hy));
    float fz = __bfloat162float(__ushort_as_bfloat16(hz));
    float fw = __bfloat162float(__ushort_as_bfloat16(hw));
    unsigned short lx = __bfloat16_as_ushort(__float2bfloat16(v.x - fx));
    unsigned short ly = __bfloat16_as_ushort(__float2bfloat16(v.y - fy));
    unsigned short lz = __bfloat16_as_ushort(__float2bfloat16(v.z - fz));
    unsigned short lw = __bfloat16_as_ushort(__float2bfloat16(v.w - fw));
    uh.x = (uint32_t)hx | ((uint32_t)hy << 16);
    uh.y = (uint32_t)hz | ((uint32_t)hw << 16);
    ul.x = (uint32_t)lx | ((uint32_t)ly << 16);
    ul.y = (uint32_t)lz | ((uint32_t)lw << 16);
}
__device__ __forceinline__ signed char q8(float q) {
    int i = __float2int_rn(q);
    i = max(-127, min(127, i));
    return (signed char)i;
}

// ================= int8 3-term GEMM =================
// A = sa[m]*(Ah + Al/254), W = sw[n]*(Wh + Wl/254); C = act((A@W + lb)*ga*BNS + be)
// CTA tile 128x64, 4 warps (2x2), warp tile 64x32, wmma s8 16x16x16, 2 int32 acc sets.
constexpr int A_LD8  = 48;                   // bytes per A smem row (32 + 16 pad)
constexpr int B_LD8  = 80;                   // bytes per B smem row (64 + 16 pad)
constexpr int A_M8   = 128 * A_LD8;          // 6144
constexpr int B_M8   = 32 * B_LD8;           // 2560
constexpr int S8_AH  = 0;
constexpr int S8_AL  = A_M8;
constexpr int S8_BH  = 2 * A_M8;             // 12288
constexpr int S8_BL  = 2 * A_M8 + B_M8;      // 14848
constexpr int STAGE8 = 2 * A_M8 + 2 * B_M8;  // 17408
constexpr int OFF_SCN8 = 2 * STAGE8;         // 34816 (64 floats)
constexpr int OFF_SH8  = OFF_SCN8 + 256;
constexpr int DSMEM8   = OFF_SH8 + 256;      // 35328 (x2 CTAs = 70.7KB)

template<int RELU>
__global__ void __launch_bounds__(128, 2) gemm_s8(
    const signed char* __restrict__ Ah, const signed char* __restrict__ Al,
    const signed char* __restrict__ Wh, const signed char* __restrict__ Wl,
    const float* __restrict__ sa, const float* __restrict__ sw,
    const float* __restrict__ lb, const float* __restrict__ ga,
    const float* __restrict__ be, float* __restrict__ C,
    int M, int K, int Nc)
{
    extern __shared__ char sm[];
    const uint32_t sbase = smem_u32(sm);

    const int tid  = threadIdx.x;
    const int warp = tid >> 5, lane = tid & 31;
    const int wm   = warp >> 1, wn = warp & 1;   // 2x2; warp tile 64x32
    const int bm0  = blockIdx.y * 128, bn0 = blockIdx.x * 64;

    if (tid < 64) {
        float sc = ga[bn0 + tid] * BNS;
        ((float*)(sm + OFF_SCN8))[tid] = sw[bn0 + tid] * sc;
        ((float*)(sm + OFF_SH8))[tid]  = fmaf(lb[bn0 + tid], sc, be[bn0 + tid]);
    }

    wmma::fragment<wmma::accumulator, 16, 16, 16, int> acc0[4][2], acc12[4][2];
#pragma unroll
    for (int i = 0; i < 4; i++)
#pragma unroll
        for (int j = 0; j < 2; j++) {
            wmma::fill_fragment(acc0[i][j], 0);
            wmma::fill_fragment(acc12[i][j], 0);
        }

    const int nK = K >> 5;

    auto issue = [&](int c) {
        const int buf = c & 1;
        const int k0  = c << 5;
        const uint32_t sb = sbase + buf * STAGE8;
        // A: 256 16B chunks per matrix (128 rows x 32 bytes), 2 per thread
#pragma unroll
        for (int t = 0; t < 2; t++) {
            int chunk = tid + (t << 7);
            int row   = chunk >> 1;
            int c16   = (chunk & 1) << 4;
            int gr    = bm0 + row;
            if (gr < M) {
                uint32_t off = (uint32_t)(row * A_LD8 + c16);
                size_t g = (size_t)gr * K + k0 + c16;
                cp16(sb + S8_AH + off, Ah + g);
                cp16(sb + S8_AL + off, Al + g);
            }
        }
        // B: 128 chunks per matrix (32 rows x 64 bytes), 1 per thread
        {
            int row = tid >> 2;
            int c16 = (tid & 3) << 4;
            uint32_t off = (uint32_t)(row * B_LD8 + c16);
            size_t g = (size_t)(k0 + row) * Nc + bn0 + c16;
            cp16(sb + S8_BH + off, Wh + g);
            cp16(sb + S8_BL + off, Wl + g);
        }
        CP_COMMIT();
    };

    issue(0);
    for (int c = 0; c < nK; c++) {
        if (c + 1 < nK) { issue(c + 1); CP_WAIT(1); }
        else            { CP_WAIT(0); }
        __syncthreads();

        const char* st = sm + (c & 1) * STAGE8;
        const signed char* sAh = (const signed char*)(st + S8_AH);
        const signed char* sAl = (const signed char*)(st + S8_AL);
        const signed char* sBh = (const signed char*)(st + S8_BH);
        const signed char* sBl = (const signed char*)(st + S8_BL);
#pragma unroll
        for (int ks = 0; ks < 2; ks++) {
            const int kk = ks << 4;
            wmma::fragment<wmma::matrix_a, 16, 16, 16, signed char, wmma::row_major> fah[4], fal[4];
#pragma unroll
            for (int i = 0; i < 4; i++) {
                wmma::load_matrix_sync(fah[i], sAh + (wm * 64 + i * 16) * A_LD8 + kk, A_LD8);
                wmma::load_matrix_sync(fal[i], sAl + (wm * 64 + i * 16) * A_LD8 + kk, A_LD8);
            }
#pragma unroll
            for (int j = 0; j < 2; j++) {
                wmma::fragment<wmma::matrix_b, 16, 16, 16, signed char, wmma::row_major> fbh, fbl;
                wmma::load_matrix_sync(fbh, sBh + kk * B_LD8 + wn * 32 + j * 16, B_LD8);
                wmma::load_matrix_sync(fbl, sBl + kk * B_LD8 + wn * 32 + j * 16, B_LD8);
#pragma unroll
                for (int i = 0; i < 4; i++) {
                    wmma::mma_sync(acc0[i][j],  fah[i], fbh, acc0[i][j]);
                    wmma::mma_sync(acc12[i][j], fah[i], fbl, acc12[i][j]);
                    wmma::mma_sync(acc12[i][j], fal[i], fbh, acc12[i][j]);
                }
            }
        }
        __syncthreads();
    }

    // epilogue: combine acc sets with /254, scale by sa*swsc, BN shift, optional ReLU
    int* st0 = (int*)(sm + warp * 2048);
    int* st1 = st0 + 256;
    const float* scn = (const float*)(sm + OFF_SCN8);
    const float* shb = (const float*)(sm + OFF_SH8);
#pragma unroll
    for (int i = 0; i < 4; i++)
#pragma unroll
        for (int j = 0; j < 2; j++) {
            __syncwarp();
            wmma::store_matrix_sync(st0, acc0[i][j], 16, wmma::mem_row_major);
            wmma::store_matrix_sync(st1, acc12[i][j], 16, wmma::mem_row_major);
            __syncwarp();
#pragma unroll
            for (int t = lane; t < 256; t += 32) {
                int r   = t >> 4, cc = t & 15;
                int gr  = bm0 + wm * 64 + i * 16 + r;
                int gcl = wn * 32 + j * 16 + cc;
                if (gr < M) {
                    float comb = (float)st0[r * 16 + cc] + (float)st1[r * 16 + cc] * (1.0f / 254.0f);
                    float o = fmaf(comb * __ldg(sa + gr), scn[gcl], shb[gcl]);
                    if (RELU) o = fmaxf(o, 0.0f);
                    C[(size_t)gr * Nc + bn0 + gcl] = o;
                }
            }
        }
}

// ---------------- activation quantizer: warp per row, 2-term int8 ----------------
template<int W>
__global__ void __launch_bounds__(256) quant_act_k(
    const float* __restrict__ X, int M,
    signed char* __restrict__ qh, signed char* __restrict__ ql, float* __restrict__ sa)
{
    const int row  = blockIdx.x * 8 + (threadIdx.x >> 5);
    const int lane = threadIdx.x & 31;
    if (row >= M) return;
    constexpr int PL = W / 128;   // float4 per lane
    const float4* xr = reinterpret_cast<const float4*>(X + (size_t)row * W);
    float4 v[PL];
    float m = 0.0f;
#pragma unroll
    for (int p = 0; p < PL; p++) {
        v[p] = xr[lane + p * 32];
        m = fmaxf(m, fmaxf(fmaxf(fabsf(v[p].x), fabsf(v[p].y)),
                           fmaxf(fabsf(v[p].z), fabsf(v[p].w))));
    }
#pragma unroll
    for (int o = 16; o > 0; o >>= 1)
        m = fmaxf(m, __shfl_xor_sync(0xffffffff, m, o));
    float sav = (m > 0.0f) ? m * (1.0f / 127.0f) : 1.0f;
    float inv = (m > 0.0f) ? 127.0f / m : 0.0f;
    if (lane == 0) sa[row] = sav;
#pragma unroll
    for (int p = 0; p < PL; p++) {
        float qx = v[p].x * inv, qy = v[p].y * inv, qz = v[p].z * inv, qw = v[p].w * inv;
        signed char hx = q8(qx), hy = q8(qy), hz = q8(qz), hw = q8(qw);
        char4 ch = make_char4(hx, hy, hz, hw);
        char4 cl = make_char4(q8((qx - (float)hx) * 254.0f), q8((qy - (float)hy) * 254.0f),
                              q8((qz - (float)hz) * 254.0f), q8((qw - (float)hw) * 254.0f));
        size_t idx = (size_t)row * (W / 4) + lane + p * 32;
        reinterpret_cast<char4*>(qh)[idx] = ch;
        reinterpret_cast<char4*>(ql)[idx] = cl;
    }
}

// ---------------- weight quantizer: thread per column, 2-term int8 ----------------
__global__ void quant_w_k(const float* __restrict__ W, int K, int Nc,
                          signed char* __restrict__ wh, signed char* __restrict__ wl,
                          float* __restrict__ sw)
{
    int col = blockIdx.x * 256 + threadIdx.x;
    if (col >= Nc) return;
    float m = 0.0f;
    for (int k = 0; k < K; k++) m = fmaxf(m, fabsf(W[(size_t)k * Nc + col]));
    float s = (m > 0.0f) ? m * (1.0f / 127.0f) : 1.0f;
    float inv = (m > 0.0f) ? 127.0f / m : 0.0f;
    sw[col] = s;
    for (int k = 0; k < K; k++) {
        float q = W[(size_t)k * Nc + col] * inv;
        signed char h = q8(q);
        wh[(size_t)k * Nc + col] = h;
        wl[(size_t)k * Nc + col] = q8((q - (float)h) * 254.0f);
    }
}

// ================= bf16 path for tiny virtual-node MLP (proven R16 kernel) =================
constexpr int A_LD   = 40;
constexpr int B_LD   = 136;
constexpr int A_MATB = 128 * A_LD * 2;
constexpr int B_MATB = 32 * B_LD * 2;
constexpr int ST_AH  = 0;
constexpr int ST_AL  = A_MATB;
constexpr int ST_BH  = 2 * A_MATB;
constexpr int ST_BL  = 2 * A_MATB + B_MATB;
constexpr int STAGE  = 2 * A_MATB + 2 * B_MATB;
constexpr int OFF_SC = 2 * STAGE;
constexpr int OFF_SH = OFF_SC + 512;
constexpr int DSMEM  = OFF_SH + 512;

template<int RELU, int SPLIT>
__global__ void __launch_bounds__(128, 2) gemm_bf16(
    const __nv_bfloat16* __restrict__ Ahi, const __nv_bfloat16* __restrict__ Alo,
    const __nv_bfloat16* __restrict__ Bhi, const __nv_bfloat16* __restrict__ Blo,
    const float* __restrict__ lb, const float* __restrict__ ga,
    const float* __restrict__ be, float* __restrict__ C,
    __nv_bfloat16* __restrict__ Chi, __nv_bfloat16* __restrict__ Clo,
    int M, int K, int Nc)
{
    extern __shared__ char sm[];
    const uint32_t sbase = smem_u32(sm);
    const int tid  = threadIdx.x;
    const int warp = tid >> 5, lane = tid & 31;
    const int wm   = warp >> 1, wn = warp & 1;
    const int bm0  = blockIdx.y * 128, bn0 = blockIdx.x * 128;

    {
        float s = ga[bn0 + tid] * BNS;
        ((float*)(sm + OFF_SC))[tid] = s;
        ((float*)(sm + OFF_SH))[tid] = fmaf(lb[bn0 + tid], s, be[bn0 + tid]);
    }

    wmma::fragment<wmma::accumulator, 16, 16, 16, float> acc[4][4];
#pragma unroll
    for (int i = 0; i < 4; i++)
#pragma unroll
        for (int j = 0; j < 4; j++) wmma::fill_fragment(acc[i][j], 0.0f);

    const int nK = K >> 5;
    auto issue = [&](int c) {
        const int buf = c & 1;
        const int k0  = c << 5;
        const uint32_t sb = sbase + buf * STAGE;
#pragma unroll
        for (int t = 0; t < 4; t++) {
            int chunk = tid + (t << 7);
            int row   = chunk >> 2;
            int col8  = (chunk & 3) << 3;
            int gr    = bm0 + row;
            if (gr < M) {
                uint32_t off = (uint32_t)(row * A_LD + col8) * 2;
                size_t g = (size_t)gr * K + k0 + col8;
                cp16(sb + ST_AH + off, Ahi + g);
                cp16(sb + ST_AL + off, Alo + g);
            }
        }
#pragma unroll
        for (int t = 0; t < 4; t++) {
            int chunk = tid + (t << 7);
            int row   = chunk >> 4;
            int col8  = (chunk & 15) << 3;
            uint32_t off = (uint32_t)(row * B_LD + col8) * 2;
            size_t g = (size_t)(k0 + row) * Nc + bn0 + col8;
            cp16(sb + ST_BH + off, Bhi + g);
            cp16(sb + ST_BL + off, Blo + g);
        }
        CP_COMMIT();
    };

    issue(0);
    for (int c = 0; c < nK; c++) {
        if (c + 1 < nK) { issue(c + 1); CP_WAIT(1); }
        else            { CP_WAIT(0); }
        __syncthreads();
        const char* st = sm + (c & 1) * STAGE;
        const __nv_bfloat16* sAh = (const __nv_bfloat16*)(st + ST_AH);
        const __nv_bfloat16* sAl = (const __nv_bfloat16*)(st + ST_AL);
        const __nv_bfloat16* sBh = (const __nv_bfloat16*)(st + ST_BH);
        const __nv_bfloat16* sBl = (const __nv_bfloat16*)(st + ST_BL);
#pragma unroll
        for (int ks = 0; ks < 2; ks++) {
            const int kk = ks << 4;
            wmma::fragment<wmma::matrix_a, 16, 16, 16, __nv_bfloat16, wmma::row_major> ah[4], al[4];
#pragma unroll
            for (int i = 0; i < 4; i++) {
                wmma::load_matrix_sync(ah[i], sAh + (wm * 64 + i * 16) * A_LD + kk, A_LD);
                wmma::load_matrix_sync(al[i], sAl + (wm * 64 + i * 16) * A_LD + kk, A_LD);
            }
#pragma unroll
            for (int j = 0; j < 4; j++) {
                wmma::fragment<wmma::matrix_b, 16, 16, 16, __nv_bfloat16, wmma::row_major> bh, bl;
                wmma::load_matrix_sync(bh, sBh + kk * B_LD + wn * 64 + j * 16, B_LD);
                wmma::load_matrix_sync(bl, sBl + kk * B_LD + wn * 64 + j * 16, B_LD);
#pragma unroll
                for (int i = 0; i < 4; i++) {
                    wmma::mma_sync(acc[i][j], ah[i], bh, acc[i][j]);
                    wmma::mma_sync(acc[i][j], ah[i], bl, acc[i][j]);
                    wmma::mma_sync(acc[i][j], al[i], bh, acc[i][j]);
                }
            }
        }
        __syncthreads();
    }

    float* stage = (float*)(sm + warp * 1280);
    const float* sc = (const float*)(sm + OFF_SC);
    const float* sh = (const float*)(sm + OFF_SH);
#pragma unroll
    for (int i = 0; i < 4; i++)
#pragma unroll
        for (int j = 0; j < 4; j++) {
            __syncwarp();
            wmma::store_matrix_sync(stage, acc[i][j], 20, wmma::mem_row_major);
            __syncwarp();
#pragma unroll
            for (int t = lane; t < 256; t += 32) {
                int r   = t >> 4, cc = t & 15;
                int gr  = bm0 + wm * 64 + i * 16 + r;
                int gcl = wn * 64 + j * 16 + cc;
                if (gr < M) {
                    float o = fmaf(stage[r * 20 + cc], sc[gcl], sh[gcl]);
                    if (RELU) o = fmaxf(o, 0.0f);
                    size_t idx = (size_t)gr * Nc + bn0 + gcl;
                    if (SPLIT) {
                        __nv_bfloat16 hi = __float2bfloat16(o);
                        Chi[idx] = hi;
                        Clo[idx] = __float2bfloat16(o - __bfloat162float(hi));
                    } else {
                        C[idx] = o;
                    }
                }
            }
        }
}

// ---------------- misc kernels ----------------
__global__ void prep_k(int* __restrict__ deg, int* __restrict__ cur) {
    int i = blockIdx.x * 256 + threadIdx.x;
    if (i < kN) { deg[i] = 0; cur[i] = 0; }
}

__global__ void split_k(const float* __restrict__ A, __nv_bfloat16* __restrict__ hi,
                        __nv_bfloat16* __restrict__ lo, int n4) {
    int i = blockIdx.x * blockDim.x + threadIdx.x;
    if (i >= n4) return;
    uint2 uh, ul;
    split4(reinterpret_cast<const float4*>(A)[i], uh, ul);
    reinterpret_cast<uint2*>(hi)[i] = uh;
    reinterpret_cast<uint2*>(lo)[i] = ul;
}

__global__ void degcount_k(const int* __restrict__ dst, int* __restrict__ deg) {
    int e = blockIdx.x * blockDim.x + threadIdx.x;
    if (e < kE) atomicAdd(&deg[__ldg(dst + e)], 1);
}

__global__ void scan_k(const int* __restrict__ deg, int* __restrict__ rowptr) {
    __shared__ int part[1024];
    __shared__ int total;
    const int t  = threadIdx.x;
    const int CH = (kN + 1023) / 1024;
    int start = t * CH;
    int end   = start + CH; if (end > kN) end = kN;
    int s = 0;
    for (int i = start; i < end; i++) s += deg[i];
    part[t] = s;
    __syncthreads();
    if (t == 0) {
        int run = 0;
        for (int j = 0; j < 1024; j++) { int v = part[j]; part[j] = run; run += v; }
        total = run;
    }
    __syncthreads();
    int run = part[t];
    for (int i = start; i < end; i++) { rowptr[i] = run; run += deg[i]; }
    if (t == 0) rowptr[kN] = total;
}

__global__ void fill_k(const int* __restrict__ src, const int* __restrict__ dst,
                       const int* __restrict__ rowptr, int* __restrict__ cur,
                       int* __restrict__ esrc) {
    int e = blockIdx.x * blockDim.x + threadIdx.x;
    if (e >= kE) return;
    int d = __ldg(dst + e);
    int pos = rowptr[d] + atomicAdd(&cur[d], 1);
    esrc[pos] = __ldg(src + e);
}

__global__ void countgscan_k(const int* __restrict__ batch, int* __restrict__ goff) {
    __shared__ int scnt[kG];
    const int t = threadIdx.x;
    for (int g = t; g < kG; g += blockDim.x) scnt[g] = 0;
    __syncthreads();
    for (int n = t; n < kN; n += blockDim.x) atomicAdd(&scnt[__ldg(batch + n)], 1);
    __syncthreads();
    if (t == 0) {
        int run = 0;
        for (int g = 0; g < kG; g++) { goff[g] = run; run += scnt[g]; }
        goff[kG] = run;
    }
}

// CSR gather aggregation (+virtual add), fp32 output
template<int F, int VIRT>
__global__ void __launch_bounds__(256) aggregate_k(
    const float* __restrict__ feat, const float* __restrict__ vf,
    const int* __restrict__ batch,
    const int* __restrict__ rowptr, const int* __restrict__ esrc,
    float* __restrict__ out)
{
    constexpr int C4  = F / 4;
    constexpr int NPB = 256 / C4;
    const int n = blockIdx.x * NPB + (threadIdx.x / C4);
    const int c = threadIdx.x & (C4 - 1);
    const float4* f4  = reinterpret_cast<const float4*>(feat);
    const float4* vf4 = reinterpret_cast<const float4*>(vf);
    float4 acc = f4[(size_t)n * C4 + c];
    if (VIRT) {
        float4 v = vf4[(size_t)__ldg(batch + n) * C4 + c];
        acc.x += v.x; acc.y += v.y; acc.z += v.z; acc.w += v.w;
    }
    const int p0 = __ldg(rowptr + n), p1 = __ldg(rowptr + n + 1);
    int p = p0;
    for (; p + 4 <= p1; p += 4) {
        int s0 = __ldg(esrc + p),     s1 = __ldg(esrc + p + 1);
        int s2 = __ldg(esrc + p + 2), s3 = __ldg(esrc + p + 3);
        float4 v0 = f4[(size_t)s0 * C4 + c];
        float4 v1 = f4[(size_t)s1 * C4 + c];
        float4 v2 = f4[(size_t)s2 * C4 + c];
        float4 v3 = f4[(size_t)s3 * C4 + c];
        if (VIRT) {
            float4 w0 = vf4[(size_t)__ldg(batch + s0) * C4 + c];
            float4 w1 = vf4[(size_t)__ldg(batch + s1) * C4 + c];
            float4 w2 = vf4[(size_t)__ldg(batch + s2) * C4 + c];
            float4 w3 = vf4[(size_t)__ldg(batch + s3) * C4 + c];
            v0.x += w0.x; v0.y += w0.y; v0.z += w0.z; v0.w += w0.w;
            v1.x += w1.x; v1.y += w1.y; v1.z += w1.z; v1.w += w1.w;
            v2.x += w2.x; v2.y += w2.y; v2.z += w2.z; v2.w += w2.w;
            v3.x += w3.x; v3.y += w3.y; v3.z += w3.z; v3.w += w3.w;
        }
        acc.x += (v0.x + v1.x) + (v2.x + v3.x);
        acc.y += (v0.y + v1.y) + (v2.y + v3.y);
        acc.z += (v0.z + v1.z) + (v2.z + v3.z);
        acc.w += (v0.w + v1.w) + (v2.w + v3.w);
    }
    for (; p < p1; p++) {
        int s = __ldg(esrc + p);
        float4 v = f4[(size_t)s * C4 + c];
        if (VIRT) {
            float4 w = vf4[(size_t)__ldg(batch + s) * C4 + c];
            v.x += w.x; v.y += w.y; v.z += w.z; v.w += w.w;
        }
        acc.x += v.x; acc.y += v.y; acc.z += v.z; acc.w += v.w;
    }
    reinterpret_cast<float4*>(out)[(size_t)n * C4 + c] = acc;
}

__global__ void pool_virt_k(const float* __restrict__ h, const int* __restrict__ goff,
                            const float* __restrict__ vf,
                            __nv_bfloat16* __restrict__ phi, __nv_bfloat16* __restrict__ plo) {
    const int g = blockIdx.x, c = threadIdx.x;
    const float4* h4 = reinterpret_cast<const float4*>(h);
    float4 a0 = reinterpret_cast<const float4*>(vf)[(size_t)g * 128 + c];
    float4 a1 = make_float4(0.f, 0.f, 0.f, 0.f);
    const int n0 = __ldg(goff + g), n1 = __ldg(goff + g + 1);
    int n = n0;
    for (; n + 2 <= n1; n += 2) {
        float4 v0 = h4[(size_t)n * 128 + c];
        float4 v1 = h4[(size_t)(n + 1) * 128 + c];
        a0.x += v0.x; a0.y += v0.y; a0.z += v0.z; a0.w += v0.w;
        a1.x += v1.x; a1.y += v1.y; a1.z += v1.z; a1.w += v1.w;
    }
    if (n < n1) {
        float4 v = h4[(size_t)n * 128 + c];
        a0.x += v.x; a0.y += v.y; a0.z += v.z; a0.w += v.w;
    }
    a0.x += a1.x; a0.y += a1.y; a0.z += a1.z; a0.w += a1.w;
    uint2 uh, ul;
    split4(a0, uh, ul);
    reinterpret_cast<uint2*>(phi)[(size_t)g * 128 + c] = uh;
    reinterpret_cast<uint2*>(plo)[(size_t)g * 128 + c] = ul;
}

__global__ void pool_mean_k(const float* __restrict__ h, const int* __restrict__ goff,
                            float* __restrict__ out) {
    const int g = blockIdx.x, c = threadIdx.x;
    const float4* h4 = reinterpret_cast<const float4*>(h);
    float4 a0 = make_float4(0.f, 0.f, 0.f, 0.f);
    float4 a1 = make_float4(0.f, 0.f, 0.f, 0.f);
    const int n0 = __ldg(goff + g), n1 = __ldg(goff + g + 1);
    int n = n0;
    for (; n + 2 <= n1; n += 2) {
        float4 v0 = h4[(size_t)n * 128 + c];
        float4 v1 = h4[(size_t)(n + 1) * 128 + c];
        a0.x += v0.x; a0.y += v0.y; a0.z += v0.z; a0.w += v0.w;
        a1.x += v1.x; a1.y += v1.y; a1.z += v1.z; a1.w += v1.w;
    }
    if (n < n1) {
        float4 v = h4[(size_t)n * 128 + c];
        a0.x += v.x; a0.y += v.y; a0.z += v.z; a0.w += v.w;
    }
    float inv = 1.0f / fmaxf((float)(n1 - n0), 1.0f);
    a0.x = (a0.x + a1.x) * inv; a0.y = (a0.y + a1.y) * inv;
    a0.z = (a0.z + a1.z) * inv; a0.w = (a0.w + a1.w) * inv;
    reinterpret_cast<float4*>(out)[(size_t)g * 128 + c] = a0;
}

__global__ void vinit_k(float* __restrict__ vf, const float* __restrict__ vemb) {
    int idx = blockIdx.x * blockDim.x + threadIdx.x;
    if (idx >= kG * kH / 4) return;
    reinterpret_cast<float4*>(vf)[idx] =
        reinterpret_cast<const float4*>(vemb)[idx & (kH / 4 - 1)];
}

// ---------------- host launcher ----------------
static void run_gemm_s8(const signed char* Ah, const signed char* Al,
                        const signed char* Wh, const signed char* Wl,
                        const float* sa, const float* sw,
                        const float* lb, const float* ga, const float* be,
                        float* C, int M, int K, int Nc, bool relu) {
    dim3 grid(Nc / 64, (M + 127) / 128);
    if (relu) gemm_s8<1><<<grid, 128, DSMEM8>>>(Ah, Al, Wh, Wl, sa, sw, lb, ga, be, C, M, K, Nc);
    else      gemm_s8<0><<<grid, 128, DSMEM8>>>(Ah, Al, Wh, Wl, sa, sw, lb, ga, be, C, M, K, Nc);
}

static void run_gemm_bf16(const __nv_bfloat16* Ahi, const __nv_bfloat16* Alo,
                          const __nv_bfloat16* Bhi, const __nv_bfloat16* Blo,
                          const float* lb, const float* ga, const float* be,
                          float* C, __nv_bfloat16* Chi, __nv_bfloat16* Clo,
                          int M, int K, int Nc, bool relu, bool split) {
    dim3 grid(Nc / 128, (M + 127) / 128);
    if (split) {
        if (relu) gemm_bf16<1,1><<<grid, 128, DSMEM>>>(Ahi, Alo, Bhi, Blo, lb, ga, be, C, Chi, Clo, M, K, Nc);
        else      gemm_bf16<0,1><<<grid, 128, DSMEM>>>(Ahi, Alo, Bhi, Blo, lb, ga, be, C, Chi, Clo, M, K, Nc);
    } else {
        if (relu) gemm_bf16<1,0><<<grid, 128, DSMEM>>>(Ahi, Alo, Bhi, Blo, lb, ga, be, C, Chi, Clo, M, K, Nc);
        else      gemm_bf16<0,0><<<grid, 128, DSMEM>>>(Ahi, Alo, Bhi, Blo, lb, ga, be, C, Chi, Clo, M, K, Nc);
    }
}

extern "C" void kernel_launch(void* const* d_in, const int* in_sizes, int n_in,
                              void* d_out, int out_size) {
    const float* x      = (const float*)d_in[0];
    const int*   ei     = (const int*)  d_in[1];
    const int*   batch  = (const int*)  d_in[2];
    const float* c1_W1  = (const float*)d_in[3];
    const float* c1_b1  = (const float*)d_in[4];
    const float* c1_g1  = (const float*)d_in[5];
    const float* c1_be1 = (const float*)d_in[6];
    const float* c1_W2  = (const float*)d_in[7];
    const float* c1_b2  = (const float*)d_in[8];
    const float* bn1_g  = (const float*)d_in[9];
    const float* bn1_b  = (const float*)d_in[10];
    const float* cs_W1  = (const float*)d_in[11];
    const float* cs_b1  = (const float*)d_in[12];
    const float* cs_g1  = (const float*)d_in[13];
    const float* cs_be1 = (const float*)d_in[14];
    const float* cs_W2  = (const float*)d_in[15];
    const float* cs_b2  = (const float*)d_in[16];
    const float* bns_g  = (const float*)d_in[17];
    const float* bns_b  = (const float*)d_in[18];
    const float* vemb   = (const float*)d_in[19];
    const float* v_W1   = (const float*)d_in[20];
    const float* v_b1   = (const float*)d_in[21];
    const float* v_g1   = (const float*)d_in[22];
    const float* v_be1  = (const float*)d_in[23];
    const float* v_W2   = (const float*)d_in[24];
    const float* v_b2   = (const float*)d_in[25];
    const float* v_g2   = (const float*)d_in[26];
    const float* v_be2  = (const float*)d_in[27];

    cudaFuncSetAttribute(gemm_s8<0>,   cudaFuncAttributeMaxDynamicSharedMemorySize, DSMEM8);
    cudaFuncSetAttribute(gemm_s8<1>,   cudaFuncAttributeMaxDynamicSharedMemorySize, DSMEM8);
    cudaFuncSetAttribute(gemm_bf16<0,0>, cudaFuncAttributeMaxDynamicSharedMemorySize, DSMEM);
    cudaFuncSetAttribute(gemm_bf16<0,1>, cudaFuncAttributeMaxDynamicSharedMemorySize, DSMEM);
    cudaFuncSetAttribute(gemm_bf16<1,0>, cudaFuncAttributeMaxDynamicSharedMemorySize, DSMEM);
    cudaFuncSetAttribute(gemm_bf16<1,1>, cudaFuncAttributeMaxDynamicSharedMemorySize, DSMEM);

    float *h, *zin, *y1, *vf, *sa, *sw;
    int *goff, *deg, *cur, *rowptr, *esrc;
    signed char *a8h, *a8l, *w8h, *w8l;
    __nv_bfloat16 *vwhi, *vwlo, *phi, *plo, *qhi, *qlo;
    cudaGetSymbolAddress((void**)&h,      g_h);
    cudaGetSymbolAddress((void**)&zin,    g_zin);
    cudaGetSymbolAddress((void**)&y1,     g_y1);
    cudaGetSymbolAddress((void**)&vf,     g_vf);
    cudaGetSymbolAddress((void**)&sa,     g_sa);
    cudaGetSymbolAddress((void**)&sw,     g_sw);
    cudaGetSymbolAddress((void**)&goff,   g_goff);
    cudaGetSymbolAddress((void**)&deg,    g_deg);
    cudaGetSymbolAddress((void**)&cur,    g_cur);
    cudaGetSymbolAddress((void**)&rowptr, g_rowptr);
    cudaGetSymbolAddress((void**)&esrc,   g_esrc);
    cudaGetSymbolAddress((void**)&a8h,    g_a8h);
    cudaGetSymbolAddress((void**)&a8l,    g_a8l);
    cudaGetSymbolAddress((void**)&w8h,    g_w8h);
    cudaGetSymbolAddress((void**)&w8l,    g_w8l);
    cudaGetSymbolAddress((void**)&vwhi,   g_vwhi);
    cudaGetSymbolAddress((void**)&vwlo,   g_vwlo);
    cudaGetSymbolAddress((void**)&phi,    g_phi);
    cudaGetSymbolAddress((void**)&plo,    g_plo);
    cudaGetSymbolAddress((void**)&qhi,    g_qhi);
    cudaGetSymbolAddress((void**)&qlo,    g_qlo);

    const int* srcI = ei;
    const int* dstI = ei + kE;

    // ---- CSR + conv1 critical chain ----
    prep_k<<<(kN + 255) / 256, 256>>>(deg, cur);
    degcount_k<<<(kE + 255) / 256, 256>>>(dstI, deg);
    scan_k<<<1, 1024>>>(deg, rowptr);
    fill_k<<<(kE + 255) / 256, 256>>>(srcI, dstI, rowptr, cur, esrc);
    quant_w_k<<<(kH2 + 255) / 256, 256>>>(c1_W1, kD, kH2, w8h + OFF_c1W1, w8l + OFF_c1W1, sw + SW_c1W1);
    aggregate_k<kD,0><<<kN / 8, 256>>>(x, nullptr, nullptr, rowptr, esrc, zin);
    quant_act_k<kD><<<(kN + 7) / 8, 256>>>(zin, kN, a8h, a8l, sa);
    run_gemm_s8(a8h, a8l, w8h + OFF_c1W1, w8l + OFF_c1W1, sa, sw + SW_c1W1,
                c1_b1, c1_g1, c1_be1, y1, kN, kD, kH2, true);
    quant_w_k<<<(kH + 255) / 256, 256>>>(c1_W2, kH2, kH, w8h + OFF_c1W2, w8l + OFF_c1W2, sw + SW_c1W2);
    quant_act_k<kH2><<<(kN + 7) / 8, 256>>>(y1, kN, a8h, a8l, sa);
    run_gemm_s8(a8h, a8l, w8h + OFF_c1W2, w8l + OFF_c1W2, sa, sw + SW_c1W2,
                c1_b2, bn1_g, bn1_b, h, kN, kH2, kH, true);

    // remaining weight quantization + bf16 splits + graph metadata
    for (int i = 0; i < kL; i++) {
        quant_w_k<<<(kH2 + 255) / 256, 256>>>(cs_W1 + (size_t)i * kH * kH2, kH, kH2,
            w8h + OFF_csW1 + (size_t)i * kH * kH2, w8l + OFF_csW1 + (size_t)i * kH * kH2,
            sw + SW_cs + i * 1536);
        quant_w_k<<<(kH + 255) / 256, 256>>>(cs_W2 + (size_t)i * kH2 * kH, kH2, kH,
            w8h + OFF_csW2 + (size_t)i * kH2 * kH, w8l + OFF_csW2 + (size_t)i * kH2 * kH,
            sw + SW_cs + i * 1536 + 1024);
    }
    split_k<<<((kH * kH2 / 4) + 255) / 256, 256>>>(v_W1, vwhi + OFF_vW1, vwlo + OFF_vW1, kH * kH2 / 4);
    split_k<<<((kH2 * kH / 4) + 255) / 256, 256>>>(v_W2, vwhi + OFF_vW2, vwlo + OFF_vW2, kH2 * kH / 4);
    vinit_k<<<(kG * kH / 4 + 255) / 256, 256>>>(vf, vemb);
    countgscan_k<<<1, 256>>>(batch, goff);

    // ---- L GIN layers with virtual node ----
    for (int i = 0; i < kL; i++) {
        aggregate_k<kH,1><<<kN / 2, 256>>>(h, vf, batch, rowptr, esrc, zin);
        quant_act_k<kH><<<(kN + 7) / 8, 256>>>(zin, kN, a8h, a8l, sa);
        run_gemm_s8(a8h, a8l, w8h + OFF_csW1 + (size_t)i * kH * kH2,
                    w8l + OFF_csW1 + (size_t)i * kH * kH2, sa, sw + SW_cs + i * 1536,
                    cs_b1 + i * kH2, cs_g1 + i * kH2, cs_be1 + i * kH2, y1, kN, kH, kH2, true);
        quant_act_k<kH2><<<(kN + 7) / 8, 256>>>(y1, kN, a8h, a8l, sa);
        run_gemm_s8(a8h, a8l, w8h + OFF_csW2 + (size_t)i * kH2 * kH,
                    w8l + OFF_csW2 + (size_t)i * kH2 * kH, sa, sw + SW_cs + i * 1536 + 1024,
                    cs_b2 + i * kH, bns_g + i * kH, bns_b + i * kH, h, kN, kH2, kH, i < kL - 1);
        if (i < kL - 1) {
            pool_virt_k<<<kG, 128>>>(h, goff, vf, phi, plo);
            run_gemm_bf16(phi, plo, vwhi + OFF_vW1, vwlo + OFF_vW1, v_b1, v_g1, v_be1,
                          nullptr, qhi, qlo, kG, kH, kH2, true, true);
            run_gemm_bf16(qhi, qlo, vwhi + OFF_vW2, vwlo + OFF_vW2, v_b2, v_g2, v_be2,
                          vf, nullptr, nullptr, kG, kH2, kH, true, false);
        }
    }

    // ---- mean-pool readout into d_out ----
    pool_mean_k<<<kG, 128>>>(h, goff, (float*)d_out);
}